// round 17
// baseline (speedup 1.0000x reference)
#include <cuda_runtime.h>
#include <cuda_fp16.h>
#include <math.h>

constexpr int TYc=128, Bc=64, TXc=400, Hc=512, Cc=512, G4c=2048;
constexpr int NBc=256, NTc=1024;

// ---------------- device scratch ----------------
__device__ float g_pctx[(size_t)TXc*Bc*Cc];                 // fp32 key proj (+bias)
__device__ __align__(16) __half g_pvh[(size_t)TXc*Bc*Cc];   // fp16 value proj (+bias)
__device__ float g_xw  [(size_t)TYc*Bc*G4c];
__device__ float g_xwT [(size_t)TYc*G4c*Bc];   // [t][4H][b]
__device__ float g_bias4[G4c];
__device__ float g_sT[2][1024*Bc];             // [k][b]; 0-511=h, 512-1023=c
__device__ float g_hq [Bc*Cc];
__device__ float g_e  [Bc*8*TXc];
__device__ float g_acc[Bc*TXc];
__device__ float g_ctxbuf[(size_t)TYc*Bc*Cc];
__device__ float g_attbuf[(size_t)TYc*Bc*Cc];
__device__ volatile unsigned g_flags [NBc*8];  // global barrier slots
__device__ volatile unsigned g_pflags[NBc*8];  // 4-group barrier slots

// smem layout (floats), 17424 floats = ~70KB -> 2 blocks/SM
constexpr int OFF_WHH =0;       // 8 x 520  = 4160
constexpr int OFF_WCB =4160;    // 2 x 1040 = 2080
constexpr int OFF_U   =6240;    // 512
constexpr int OFF_WC  =6752;    // 512
constexpr int OFF_HQ  =7264;    // 512
constexpr int OFF_RED =7776;    // 16 x 520 = 8320 (A); 16x132 (B); 16x128 (E)
constexpr int OFF_GATE=16096;   // 512
constexpr int OFF_SW  =16608;   // 2 x 408 = 816
constexpr int SMEM_FLOATS=17424;

__device__ __forceinline__ float sigf(float x){ return 1.0f/(1.0f+__expf(-x)); }
__device__ __forceinline__ float tanh_acc(float x){
    float e=__expf(2.0f*fabsf(x));
    float r=1.0f-2.0f/(e+1.0f);
    return copysignf(r,x);
}
__device__ __forceinline__ float tanh_fast(float x){
    float r; asm("tanh.approx.f32 %0,%1;":"=f"(r):"f"(x)); return r;
}

// ---- flag-based all-to-all grid barrier (256 blocks) ----
__device__ __forceinline__ void gsync(unsigned gen){
    __syncthreads();
    if(threadIdx.x==0){ __threadfence(); g_flags[blockIdx.x*8]=gen; }
    if(threadIdx.x<NBc){
        while(g_flags[threadIdx.x*8]<gen){}
    }
    __syncthreads();
    if(threadIdx.x==0) __threadfence();
    __syncthreads();
}
// ---- 4-block group barrier (blocks sharing a batch element) ----
__device__ __forceinline__ void psync(unsigned gen){
    __syncthreads();
    if(threadIdx.x==0){ __threadfence(); g_pflags[blockIdx.x*8]=gen; }
    if(threadIdx.x<4){
        int p=(blockIdx.x&~3)+threadIdx.x;
        while(g_pflags[p*8]<gen){}
    }
    __syncthreads();
    if(threadIdx.x==0) __threadfence();
    __syncthreads();
}

// ---------------- precompute GEMMs (R13 version, unchanged) ----------------
__global__ void mega_sgemm(const float* __restrict__ ctx,
                           const float* __restrict__ Wc,const float* __restrict__ bc,
                           const float* __restrict__ Wv,const float* __restrict__ bv,
                           const float* __restrict__ yemb,const float* __restrict__ Wih){
    const int K=512;
    int bid=blockIdx.x;
    const float *A,*Bm,*bp; float* Cout=nullptr; __half* Hout=nullptr;
    int N,bm,bn;
    if(bid<800){        A=ctx;  Bm=Wc;  bp=bc;      Cout=g_pctx; N=512;
                        bm=(bid>>2)*128; bn=(bid&3)*128; }
    else if(bid<1600){  int l=bid-800;
                        A=ctx;  Bm=Wv;  bp=bv;      Hout=g_pvh;  N=512;
                        bm=(l>>2)*128; bn=(l&3)*128; }
    else {              int l=bid-1600;
                        A=yemb; Bm=Wih; bp=g_bias4; Cout=g_xw;   N=2048;
                        bm=(l>>4)*128; bn=(l&15)*128; }
    __shared__ float As[8][128], Bs[8][128];
    int tid=threadIdx.x;
    int lr=tid>>1, lc=(tid&1)*4;
    int ty=tid>>4, tx=tid&15;
    float acc[8][8]={};
    const float* Ap=A+(size_t)(bm+lr)*K+lc;
    const float* Bp=Bm+(size_t)(bn+lr)*K+lc;
    float4 a4=*(const float4*)(Ap);
    float4 b4=*(const float4*)(Bp);
    for(int k0=0;k0<K;k0+=8){
        As[lc][lr]=a4.x; As[lc+1][lr]=a4.y; As[lc+2][lr]=a4.z; As[lc+3][lr]=a4.w;
        Bs[lc][lr]=b4.x; Bs[lc+1][lr]=b4.y; Bs[lc+2][lr]=b4.z; Bs[lc+3][lr]=b4.w;
        __syncthreads();
        if(k0+8<K){ a4=*(const float4*)(Ap+k0+8); b4=*(const float4*)(Bp+k0+8); }
#pragma unroll
        for(int kk=0;kk<8;kk++){
            float ar[8],br[8];
            *(float4*)&ar[0]=*(const float4*)&As[kk][ty*8];
            *(float4*)&ar[4]=*(const float4*)&As[kk][ty*8+4];
            *(float4*)&br[0]=*(const float4*)&Bs[kk][tx*8];
            *(float4*)&br[4]=*(const float4*)&Bs[kk][tx*8+4];
#pragma unroll
            for(int i=0;i<8;i++)
#pragma unroll
                for(int j=0;j<8;j++) acc[i][j]=fmaf(ar[i],br[j],acc[i][j]);
        }
        __syncthreads();
    }
#pragma unroll
    for(int i=0;i<8;i++){
        size_t m=bm+ty*8+i;
#pragma unroll
        for(int j=0;j<8;j+=4){
            int n=bn+tx*8+j;
            float4 o;
            o.x=acc[i][j+0]+bp[n+0]; o.y=acc[i][j+1]+bp[n+1];
            o.z=acc[i][j+2]+bp[n+2]; o.w=acc[i][j+3]+bp[n+3];
            if(Hout){
                __half2 p0=__floats2half2_rn(o.x,o.y);
                __half2 p1=__floats2half2_rn(o.z,o.w);
                uint2 raw; raw.x=*(unsigned*)&p0; raw.y=*(unsigned*)&p1;
                *(uint2*)&Hout[m*(size_t)N+n]=raw;
            } else {
                *(float4*)&Cout[m*(size_t)N+n]=o;
            }
        }
    }
}

__global__ void transpose_xw(){
    __shared__ float tl[64][33];
    int j0=blockIdx.x*32, t=blockIdx.y;
    for(int f=threadIdx.x; f<2048; f+=256){ int b=f>>5, j=f&31;
        tl[b][j]=g_xw[((size_t)t*64+b)*2048 + j0+j]; }
    __syncthreads();
    for(int f=threadIdx.x; f<2048; f+=256){ int j=f>>6, b=f&63;
        g_xwT[(size_t)t*131072 + (size_t)(j0+j)*64 + b]=tl[b][j]; }
}

__global__ void init_state(const float* __restrict__ h0,const float* __restrict__ c0,
                           const float* __restrict__ cov,
                           const float* __restrict__ bi,const float* __restrict__ bh){
    int i=blockIdx.x*256+threadIdx.x;
    if(i<Bc*Hc){ int b=i>>9,u=i&511; g_sT[0][u*64+b]=h0[i]; g_sT[0][(512+u)*64+b]=c0[i]; }
    if(i<Bc*TXc) g_acc[i]=cov[i];
    if(i<G4c) g_bias4[i]=bi[i]+bh[i];
    if(i<NBc*8){ g_flags[i]=0; g_pflags[i]=0; }
}

// ---------------- persistent decoder: 256 blocks, 2/SM ----------------
__global__ void __launch_bounds__(NTc,2)
decoder_persistent(const float* __restrict__ xmask,const float* __restrict__ ymask,
                   const float* __restrict__ W_hh,const float* __restrict__ W_comb,
                   const float* __restrict__ U_att,const float* __restrict__ W_cov,
                   float* __restrict__ o_hs,float* __restrict__ o_cs,
                   float* __restrict__ o_ss,
                   float* __restrict__ o_dists,float* __restrict__ o_Cs){
    extern __shared__ float sm[];
    const int tid=threadIdx.x, bk=blockIdx.x;
    const int wid=tid>>5, lane=tid&31;
    unsigned gen=0, pgen=0;

    // preload: 8 W_hh rows (2 u x 4 gates), 2 W_comb rows, U/Wc consts
    for(int f=tid;f<8*512;f+=NTc){ int jr=f>>9,k=f&511;
        sm[OFF_WHH + jr*520 + k] =
            W_hh[(size_t)((jr>>1)*512 + bk*2 + (jr&1))*512 + k]; }
    for(int f=tid;f<2*1024;f+=NTc){ int c=f>>10,k=f&1023;
        sm[OFF_WCB + c*1040 + k] = W_comb[(size_t)(bk*2+c)*1024 + k]; }
    for(int f=tid;f<512;f+=NTc){
        sm[OFF_U+f]=U_att[f]; sm[OFF_WC+f]=W_cov[f]; }
    __syncthreads();

    const int cb=bk>>2;      // batch element owned in C/E
    const int cq=bk&3;       // quarter (ts-quarter in C, c-quarter in E)

    for(int t=0;t<TYc;t++){
        const int ph=t&1;

        // ===== A: gates rows (2u x 4g) x 64 b, K=512 =====
        __syncthreads();   // protect RED vs prior E
        {
            const int ks=tid>>6, sub=tid&63;
            const int jr=sub>>3, bg=sub&7;
            const float* hT=g_sT[ph];
            float acc[8]={};
#pragma unroll 4
            for(int kk=0;kk<32;kk++){
                int k=ks*32+kk;
                float4 v0=*(const float4*)&hT[(size_t)k*64+bg*8];
                float4 v1=*(const float4*)&hT[(size_t)k*64+bg*8+4];
                float w=sm[OFF_WHH + jr*520 + k];
                acc[0]=fmaf(w,v0.x,acc[0]); acc[1]=fmaf(w,v0.y,acc[1]);
                acc[2]=fmaf(w,v0.z,acc[2]); acc[3]=fmaf(w,v0.w,acc[3]);
                acc[4]=fmaf(w,v1.x,acc[4]); acc[5]=fmaf(w,v1.y,acc[5]);
                acc[6]=fmaf(w,v1.z,acc[6]); acc[7]=fmaf(w,v1.w,acc[7]);
            }
            *(float4*)&sm[OFF_RED + ks*520 + jr*64 + bg*8]  =*(float4*)&acc[0];
            *(float4*)&sm[OFF_RED + ks*520 + jr*64 + bg*8+4]=*(float4*)&acc[4];
        }
        __syncthreads();
        if(tid<512){
            int jr=tid>>6, b=tid&63;
            float s=0.f;
#pragma unroll
            for(int q=0;q<16;q++) s+=sm[OFF_RED + q*520 + jr*64 + b];
            sm[OFF_GATE + jr*64 + b]=s;
        }
        __syncthreads();
        if(tid<128){
            int ui=tid>>6, b=tid&63;
            int u=bk*2+ui;
            const float* xwT=&g_xwT[(size_t)t*131072];
            float gi=sm[OFF_GATE+(0*2+ui)*64+b]+xwT[(size_t)(0*512+u)*64+b];
            float gf=sm[OFF_GATE+(1*2+ui)*64+b]+xwT[(size_t)(1*512+u)*64+b];
            float gg=sm[OFF_GATE+(2*2+ui)*64+b]+xwT[(size_t)(2*512+u)*64+b];
            float go=sm[OFF_GATE+(3*2+ui)*64+b]+xwT[(size_t)(3*512+u)*64+b];
            float ho=g_sT[ph][u*64+b];
            float co=g_sT[ph][(512+u)*64+b];
            float c1=sigf(gf)*co+sigf(gi)*tanh_acc(gg);
            float h1=sigf(go)*tanh_acc(c1);
            float m=ymask[t*64+b];
            h1=m*h1+(1.0f-m)*ho;
            c1=m*c1+(1.0f-m)*co;
            g_sT[ph^1][u*64+b]=h1;
            g_sT[ph^1][(512+u)*64+b]=c1;
            size_t oo=((size_t)t*64+b)*512+u;
            o_hs[oo]=h1; o_ss[oo]=h1; o_cs[oo]=c1;
        }
        gsync(++gen);

        // ===== B: hq rows (2 c) x 64 b, K=1024 =====
        {
            const int ks=tid>>6, sub=tid&63;
            const int cl=sub>>5, bg=sub&31;
            const float* sT=g_sT[ph^1];
            float a0=0.f,a1=0.f;
#pragma unroll 4
            for(int kk=0;kk<64;kk++){
                int k=ks*64+kk;
                float2 v=*(const float2*)&sT[(size_t)k*64+bg*2];
                float w=sm[OFF_WCB + cl*1040 + k];
                a0=fmaf(w,v.x,a0); a1=fmaf(w,v.y,a1);
            }
            float2 st; st.x=a0; st.y=a1;
            *(float2*)&sm[OFF_RED + ks*132 + cl*64 + bg*2]=st;
        }
        __syncthreads();
        if(tid<128){
            int cl=tid>>6, b=tid&63;
            float s=0.f;
#pragma unroll
            for(int q=0;q<16;q++) s+=sm[OFF_RED + q*132 + cl*64 + b];
            g_hq[b*512 + bk*2 + cl]=s;
        }
        gsync(++gen);

        // ===== C: scores for (cb, ts in [cq*100, +100)) =====
        {
            for(int f=tid;f<512;f+=NTc) sm[OFF_HQ+f]=g_hq[cb*512+f];
            __syncthreads();
            for(int i=0;i<4;i++){
                int tsl=wid+32*i;
                if(tsl<100){
                    int ts=cq*100+tsl;
                    float cov=g_acc[cb*400+ts];
                    float xm=xmask[ts*64+cb];
                    const float* pc=&g_pctx[((size_t)ts*64+cb)*512];
                    float a[8]={};
#pragma unroll
                    for(int ii=0;ii<16;ii++){
                        int c=ii*32+lane;
                        float arg=pc[c]+sm[OFF_HQ+c]+cov*sm[OFF_WC+c];
                        a[ii>>1]=fmaf(tanh_fast(arg),sm[OFF_U+c],a[ii>>1]);
                    }
#pragma unroll
                    for(int hh=0;hh<8;hh++){
                        float s=a[hh]*xm;
#pragma unroll
                        for(int o=16;o>0;o>>=1) s+=__shfl_xor_sync(0xffffffffu,s,o);
                        if(lane==0) g_e[(cb*8+hh)*400+ts]=s;
                    }
                }
            }
        }
        psync(++pgen);   // the 4 blocks of this batch element

        // ===== E: softmax (2 heads) + context (128 c) =====
        {
            if(wid<2){
                const int hh=cq*2+wid;
                const float* ep=&g_e[(cb*8+hh)*400];
                float ev[13]; float mx=-3.4e38f;
#pragma unroll
                for(int i=0;i<13;i++){ int ts=lane+32*i;
                    float v=(ts<400)?ep[ts]:-3.4e38f; ev[i]=v; mx=fmaxf(mx,v); }
#pragma unroll
                for(int o=16;o>0;o>>=1) mx=fmaxf(mx,__shfl_xor_sync(0xffffffffu,mx,o));
                float sum=0.f;
#pragma unroll
                for(int i=0;i<13;i++){ int ts=lane+32*i;
                    if(ts<400){ float v=__expf(ev[i]-mx)*xmask[ts*64+cb]; ev[i]=v; sum+=v; } }
#pragma unroll
                for(int o=16;o>0;o>>=1) sum+=__shfl_xor_sync(0xffffffffu,sum,o);
                float inv=1.0f/(sum+1e-6f);
#pragma unroll
                for(int i=0;i<13;i++){ int ts=lane+32*i;
                    if(ts<400){
                        float w=ev[i]*inv;
                        sm[OFF_SW + wid*408 + ts]=w;
                        if(cq==0&&wid==0){
                            float a=g_acc[cb*400+ts];
                            o_Cs[((size_t)t*64+cb)*400+ts]=a;
                            o_dists[((size_t)t*64+cb)*400+ts]=w;
                            g_acc[cb*400+ts]=a+w;
                        }
                    } }
            }
            __syncthreads();
            {
                const int tq=tid>>6, cg=tid&63;
                const int c=cq*128+cg*2, lh=cg>>5;
                const __half* pvp=&g_pvh[(size_t)cb*512 + c];
                float a0=0.f,a1=0.f;
                int t0=tq*25;
#pragma unroll 5
                for(int tt=0;tt<25;tt++){
                    int ts=t0+tt;
                    unsigned raw=*(const unsigned*)(pvp+(size_t)ts*32768);
                    float2 f=__half22float2(*(__half2*)&raw);
                    float wv=sm[OFF_SW + lh*408 + ts];
                    a0=fmaf(f.x,wv,a0); a1=fmaf(f.y,wv,a1);
                }
                float2 st; st.x=a0; st.y=a1;
                *(float2*)&sm[OFF_RED + tq*128 + cg*2]=st;
            }
            __syncthreads();
            if(tid<128){
                float s=0.f;
#pragma unroll
                for(int q=0;q<16;q++) s+=sm[OFF_RED + q*128 + tid];
                g_ctxbuf[((size_t)t*64+cb)*512 + cq*128 + tid]=s;
            }
        }
        // no trailing gsync: E outputs consumed post-kernel; g_acc/g_e
        // consumers at t+1 are ordered by the A/B gsyncs.
    }
}

// ---------------- deferred: att = ctx @ W_concat^T ----------------
__global__ void att_gemm(const float* __restrict__ Wcat){
    const int K=512, N=512;
    __shared__ float As[8][128], Bs[8][128];
    int bm=blockIdx.y*128, bn=blockIdx.x*128;
    int tid=threadIdx.x;
    int lr=tid>>1, lc=(tid&1)*4;
    int ty=tid>>4, tx=tid&15;
    float acc[8][8]={};
    const float* Ap=g_ctxbuf+(size_t)(bm+lr)*K+lc;
    const float* Bp=Wcat+(size_t)(bn+lr)*K+lc;
    float4 a4=*(const float4*)(Ap);
    float4 b4=*(const float4*)(Bp);
    for(int k0=0;k0<K;k0+=8){
        As[lc][lr]=a4.x; As[lc+1][lr]=a4.y; As[lc+2][lr]=a4.z; As[lc+3][lr]=a4.w;
        Bs[lc][lr]=b4.x; Bs[lc+1][lr]=b4.y; Bs[lc+2][lr]=b4.z; Bs[lc+3][lr]=b4.w;
        __syncthreads();
        if(k0+8<K){ a4=*(const float4*)(Ap+k0+8); b4=*(const float4*)(Bp+k0+8); }
#pragma unroll
        for(int kk=0;kk<8;kk++){
            float ar[8],br[8];
            *(float4*)&ar[0]=*(const float4*)&As[kk][ty*8];
            *(float4*)&ar[4]=*(const float4*)&As[kk][ty*8+4];
            *(float4*)&br[0]=*(const float4*)&Bs[kk][tx*8];
            *(float4*)&br[4]=*(const float4*)&Bs[kk][tx*8+4];
#pragma unroll
            for(int i=0;i<8;i++)
#pragma unroll
                for(int j=0;j<8;j++) acc[i][j]=fmaf(ar[i],br[j],acc[i][j]);
        }
        __syncthreads();
    }
#pragma unroll
    for(int i=0;i<8;i++){
        size_t m=bm+ty*8+i;
#pragma unroll
        for(int j=0;j<8;j+=4){
            *(float4*)&g_attbuf[m*N+bn+tx*8+j]=*(float4*)&acc[i][j];
        }
    }
}

// ---------------- deferred LayerNorm ----------------
__global__ void ln_out(const float* __restrict__ lng,const float* __restrict__ lnb,
                       float* __restrict__ o_atts){
    __shared__ float red[16];
    int r=blockIdx.x, tid=threadIdx.x;
    int lane=tid&31, wd=tid>>5;
    float v0=g_attbuf[(size_t)r*512+tid];
    float v1=g_attbuf[(size_t)r*512+256+tid];
    float s=v0+v1;
#pragma unroll
    for(int o=16;o>0;o>>=1) s+=__shfl_xor_sync(0xffffffffu,s,o);
    if(lane==0) red[wd]=s;
    __syncthreads();
    float mu=0.f;
#pragma unroll
    for(int i=0;i<8;i++) mu+=red[i];
    mu*=(1.0f/512.0f);
    __syncthreads();
    float d0=v0-mu, d1=v1-mu;
    float s2=d0*d0+d1*d1;
#pragma unroll
    for(int o=16;o>0;o>>=1) s2+=__shfl_xor_sync(0xffffffffu,s2,o);
    if(lane==0) red[wd]=s2;
    __syncthreads();
    float var=0.f;
#pragma unroll
    for(int i=0;i<8;i++) var+=red[i];
    var*=(1.0f/512.0f);
    float inv=rsqrtf(var+1e-5f);
    o_atts[(size_t)r*512+tid]     =d0*inv*lng[tid]     +lnb[tid];
    o_atts[(size_t)r*512+256+tid] =d1*inv*lng[256+tid] +lnb[256+tid];
}

extern "C" void kernel_launch(void* const* d_in,const int* in_sizes,int n_in,
                              void* d_out,int out_size){
    const float* y_emb   =(const float*)d_in[0];
    const float* context =(const float*)d_in[1];
    const float* h0      =(const float*)d_in[2];
    const float* c0      =(const float*)d_in[3];
    const float* xmask   =(const float*)d_in[4];
    const float* ymask   =(const float*)d_in[5];
    const float* cov0    =(const float*)d_in[6];
    const float* W_ih    =(const float*)d_in[7];
    const float* W_hh    =(const float*)d_in[8];
    const float* b_ih    =(const float*)d_in[9];
    const float* b_hh    =(const float*)d_in[10];
    const float* Wc_att  =(const float*)d_in[11];
    const float* b_att   =(const float*)d_in[12];
    const float* Wv_att  =(const float*)d_in[13];
    const float* bv_att  =(const float*)d_in[14];
    const float* W_comb  =(const float*)d_in[15];
    const float* U_att   =(const float*)d_in[16];
    const float* W_cov   =(const float*)d_in[17];
    const float* W_concat=(const float*)d_in[18];
    const float* ln_g    =(const float*)d_in[19];
    const float* ln_b    =(const float*)d_in[20];

    float* out    =(float*)d_out;
    float* o_hs   =out;
    float* o_cs   =o_hs+(size_t)TYc*Bc*Hc;
    float* o_ss   =o_cs+(size_t)TYc*Bc*Hc;
    float* o_atts =o_ss+(size_t)TYc*Bc*Hc;
    float* o_dists=o_atts+(size_t)TYc*Bc*Cc;
    float* o_Cs   =o_dists+(size_t)TYc*Bc*TXc;

    init_state<<<128,256>>>(h0,c0,cov0,b_ih,b_hh);
    mega_sgemm<<<2624,256>>>(context,Wc_att,b_att,Wv_att,bv_att,y_emb,W_ih);
    transpose_xw<<<dim3(64,128),256>>>();

    cudaFuncSetAttribute(decoder_persistent,
        cudaFuncAttributeMaxDynamicSharedMemorySize, SMEM_FLOATS*4);
    decoder_persistent<<<NBc,NTc,SMEM_FLOATS*4>>>(xmask,ymask,W_hh,W_comb,U_att,W_cov,
        o_hs,o_cs,o_ss,o_dists,o_Cs);

    att_gemm<<<dim3(4,64),256>>>(W_concat);
    ln_out<<<TYc*Bc,256>>>(ln_g,ln_b,o_atts);
}